// round 1
// baseline (speedup 1.0000x reference)
#include <cuda_runtime.h>
#include <cuda_bf16.h>
#include <math.h>

#define H 512
#define W 512
#define BATCH 16
#define NPIX (H*W)
#define CA 0.955f
#define CB 1.3693f
#define CINF 1e6f
#define BIG 1e30f

#define LBLK 256
#define BPI 16           // loss blocks per image
#define NLB (BATCH*BPI)  // 256 loss blocks

// ---------------- device scratch (no allocations allowed) ----------------
__device__ float g_dist[BATCH*NPIX];   // 16 MB distance maps
__device__ float g_mx[BATCH];          // per-image max distance
__device__ int   g_flags[BATCH];       // bit0 = has_fg(any 1), bit1 = has_bg(any 0)
__device__ float g_part[NLB*5];        // per-block partials: F, Bnd, P, T, PT

// ---------------- scan helpers (512 threads = 16 warps) ----------------
__device__ __forceinline__ float scan_prefix_min(float v, int lane, int wid,
                                                 float* wtot, float* wexc) {
    #pragma unroll
    for (int d = 1; d < 32; d <<= 1) {
        float o = __shfl_up_sync(0xffffffffu, v, d);
        if (lane >= d) v = fminf(v, o);
    }
    if (lane == 31) wtot[wid] = v;
    __syncthreads();
    if (wid == 0) {
        float x = (lane < 16) ? wtot[lane] : BIG;
        #pragma unroll
        for (int d = 1; d < 16; d <<= 1) {
            float o = __shfl_up_sync(0xffffffffu, x, d);
            if (lane >= d) x = fminf(x, o);
        }
        float e = __shfl_up_sync(0xffffffffu, x, 1);
        if (lane == 0) e = BIG;
        if (lane < 16) wexc[lane] = e;
    }
    __syncthreads();
    return fminf(v, wexc[wid]);
}

__device__ __forceinline__ float scan_suffix_min(float v, int lane, int wid,
                                                 float* wtot, float* wexc) {
    #pragma unroll
    for (int d = 1; d < 32; d <<= 1) {
        float o = __shfl_down_sync(0xffffffffu, v, d);
        if (lane + d < 32) v = fminf(v, o);
    }
    if (lane == 0) wtot[wid] = v;
    __syncthreads();
    if (wid == 0) {
        float x = (lane < 16) ? wtot[lane] : BIG;
        #pragma unroll
        for (int d = 1; d < 16; d <<= 1) {
            float o = __shfl_down_sync(0xffffffffu, x, d);
            if (lane + d < 16) x = fminf(x, o);
        }
        float e = __shfl_down_sync(0xffffffffu, x, 1);
        if (lane >= 15) e = BIG;
        if (lane < 16) wexc[lane] = e;
    }
    __syncthreads();
    return fminf(v, wexc[wid]);
}

// horizontal 3-wide OR / AND (in-bounds only) of mask bits for row r, column j
__device__ __forceinline__ void hor3(const unsigned* mb, int r, int j,
                                     int& orr, int& ann) {
    const unsigned* row = mb + r * 16;
    int b  = (int)((row[j >> 5] >> (j & 31)) & 1u);
    int bl = (j > 0)     ? (int)((row[(j - 1) >> 5] >> ((j - 1) & 31)) & 1u) : 0;
    int br = (j < W - 1) ? (int)((row[(j + 1) >> 5] >> ((j + 1) & 31)) & 1u) : 0;
    orr = b | bl | br;
    ann = b & ((j > 0) ? bl : 1) & ((j < W - 1) ? br : 1);
}

// ---------------- chamfer distance transform: one block per image ----------------
__global__ __launch_bounds__(512) void dt_kernel(const int* __restrict__ target) {
    const int img = blockIdx.x;
    const int* tg = target + img * NPIX;
    float* dd = g_dist + img * NPIX;
    const int j = threadIdx.x;
    const int lane = j & 31;
    const int wid = j >> 5;

    __shared__ unsigned mbits[H * 16];   // 32 KB mask bitmap
    __shared__ float prevd[W + 2];       // previous row with INF padding
    __shared__ float wtot[16];
    __shared__ float wexc[16];
    __shared__ int sflag[2];

    if (j < 2) sflag[j] = 0;

    // ---- build mask bitmap + flags ----
    bool any1 = false, any0 = false;
    #pragma unroll 4
    for (int r = 0; r < H; r++) {
        int v = tg[r * W + j];
        unsigned b = __ballot_sync(0xffffffffu, v != 0);
        if (lane == 0) mbits[r * 16 + wid] = b;
        any1 |= (v != 0);
        any0 |= (v == 0);
    }
    __syncthreads();
    if (__any_sync(0xffffffffu, any1) && lane == 0) atomicOr(&sflag[0], 1);
    if (__any_sync(0xffffffffu, any0) && lane == 0) atomicOr(&sflag[1], 1);
    __syncthreads();
    const int hasb = sflag[0] & sflag[1];

    // ---- forward chamfer pass (fused seed computation) ----
    prevd[j + 1] = CINF;
    if (j == 0) { prevd[0] = CINF; prevd[W + 1] = CINF; }
    __syncthreads();

    const float aj = CA * (float)j;
    int orA = 0, andA = 1, orB, andB, orC, andC;
    hor3(mbits, 0, j, orB, andB);

    for (int i = 0; i < H; i++) {
        if (i < H - 1) hor3(mbits, i + 1, j, orC, andC);
        else           { orC = 0; andC = 1; }
        int seed;
        if (hasb) {
            seed = (((orA | orB | orC) == 1) && ((andA & andB & andC) == 0)) ? 1 : 0;
        } else {
            seed = (((mbits[i * 16 + (j >> 5)] >> (j & 31)) & 1u) == 0u) ? 1 : 0;
        }
        float drow = seed ? 0.0f : CINF;
        float m = fminf(fminf(drow, prevd[j + 1] + CA),
                        fminf(prevd[j] + CB, prevd[j + 2] + CB));
        float v = m - aj;
        v = scan_prefix_min(v, lane, wid, wtot, wexc);
        float cur = aj + v;
        dd[i * W + j] = cur;
        prevd[j + 1] = cur;   // safe: all prevd reads happened before scan's first barrier
        orA = orB; andA = andB; orB = orC; andB = andC;
        __syncthreads();
    }

    // ---- backward chamfer pass (reversed both dims, bit-matching arithmetic) ----
    prevd[j + 1] = CINF;
    if (j == 0) { prevd[0] = CINF; prevd[W + 1] = CINF; }
    __syncthreads();

    const float ajr = CA * (float)(W - 1 - j);
    float lmax = 0.0f;
    float dnext = dd[(H - 1) * W + j];
    for (int i = H - 1; i >= 0; i--) {
        float drow = dnext;
        if (i > 0) dnext = dd[(i - 1) * W + j];
        // neighbors in original coords: up=(i+1,j)+A, diag (i+1,j+1)+B and (i+1,j-1)+B
        float m = fminf(fminf(drow, prevd[j + 1] + CA),
                        fminf(prevd[j + 2] + CB, prevd[j] + CB));
        float v = m - ajr;
        v = scan_suffix_min(v, lane, wid, wtot, wexc);
        float cur = ajr + v;
        dd[i * W + j] = cur;
        lmax = fmaxf(lmax, cur);
        prevd[j + 1] = cur;
        __syncthreads();
    }

    // ---- per-image max + flags ----
    #pragma unroll
    for (int d = 16; d > 0; d >>= 1)
        lmax = fmaxf(lmax, __shfl_xor_sync(0xffffffffu, lmax, d));
    if (lane == 0) wtot[wid] = lmax;
    __syncthreads();
    if (j == 0) {
        float mm = 0.0f;
        for (int w = 0; w < 16; w++) mm = fmaxf(mm, wtot[w]);
        g_mx[img] = mm;
        g_flags[img] = sflag[0] | (sflag[1] << 1);
    }
}

// ---------------- loss partial sums ----------------
__global__ __launch_bounds__(LBLK) void loss_partial(const float* __restrict__ pred,
                                                     const int* __restrict__ target) {
    const int img = blockIdx.x / BPI;
    const int sub = blockIdx.x % BPI;
    const int base = img * NPIX;
    const float mx = g_mx[img];
    const int hfg = g_flags[img] & 1;
    const float inv = 1.0f / fmaxf(mx, 1e-12f);
    const int usediv = (mx > 0.0f) ? 1 : 0;

    float sF = 0.f, sB = 0.f, sP = 0.f, sT = 0.f, sPT = 0.f;
    for (int idx = sub * LBLK + threadIdx.x; idx < NPIX; idx += BPI * LBLK) {
        float x = pred[base + idx];
        int tv = target[base + idx];
        float d = g_dist[base + idx];
        float p = 1.0f / (1.0f + expf(-x));
        float ax = fabsf(x);
        float bce = log1pf(expf(-ax)) + (tv ? fmaxf(-x, 0.0f) : fmaxf(x, 0.0f));
        float pt = tv ? p : (1.0f - p);
        float omp = 1.0f - pt;
        float alpha = tv ? 0.25f : 0.75f;
        sF += alpha * omp * omp * bce;
        float dn = hfg ? (usediv ? d * inv : d) : 1.0f;
        sB += omp * (1.0f + dn);
        sP += p;
        if (tv) { sT += 1.0f; sPT += p; }
    }

    float vals[5] = {sF, sB, sP, sT, sPT};
    #pragma unroll
    for (int k = 0; k < 5; k++) {
        float v = vals[k];
        #pragma unroll
        for (int d = 16; d > 0; d >>= 1) v += __shfl_xor_sync(0xffffffffu, v, d);
        vals[k] = v;
    }
    __shared__ float s5[LBLK / 32][5];
    int lane = threadIdx.x & 31, wid = threadIdx.x >> 5;
    if (lane == 0) {
        #pragma unroll
        for (int k = 0; k < 5; k++) s5[wid][k] = vals[k];
    }
    __syncthreads();
    if (threadIdx.x == 0) {
        #pragma unroll
        for (int k = 0; k < 5; k++) {
            float a = 0.f;
            for (int w = 0; w < LBLK / 32; w++) a += s5[w][k];
            g_part[blockIdx.x * 5 + k] = a;
        }
    }
}

// ---------------- final combine ----------------
__global__ void loss_final(const float* __restrict__ lv, float* __restrict__ out,
                           int out_size) {
    __shared__ double sd[BATCH][4];  // F, Bnd, diceterm, iouterm
    int t = threadIdx.x;
    if (t < BATCH) {
        double F = 0, Bd = 0, P = 0, T = 0, PT = 0;
        for (int b = 0; b < BPI; b++) {
            const float* pp = g_part + (t * BPI + b) * 5;
            F += pp[0]; Bd += pp[1]; P += pp[2]; T += pp[3]; PT += pp[4];
        }
        double total = P + T;
        double uni = total - PT;
        sd[t][0] = F;
        sd[t][1] = Bd;
        sd[t][2] = (2.0 * PT + 1e-6) / (total + 1e-6);
        sd[t][3] = (PT + 1e-6) / (uni + 1e-6);
    }
    __syncthreads();
    if (t == 0) {
        double F = 0, Bd = 0, D = 0, I = 0;
        for (int b = 0; b < BATCH; b++) {
            F += sd[b][0]; Bd += sd[b][1]; D += sd[b][2]; I += sd[b][3];
        }
        double N = (double)BATCH * (double)NPIX;
        double focal = F / N;
        double bnd   = Bd / N;
        double dice  = 1.0 - D / (double)BATCH;
        double iou   = 1.0 - I / (double)BATCH;
        double l0 = (double)lv[0], l1 = (double)lv[1], l2 = (double)lv[2], l3 = (double)lv[3];
        double tot = exp(-l0) * focal + l0
                   + exp(-l1) * dice  + l1
                   + exp(-l2) * bnd   + l2
                   + exp(-l3) * iou   + l3;
        if (out_size > 0) out[0] = (float)tot;
        if (out_size > 1) out[1] = (float)focal;
        if (out_size > 2) out[2] = (float)dice;
        if (out_size > 3) out[3] = (float)bnd;
        if (out_size > 4) out[4] = (float)iou;
    }
}

extern "C" void kernel_launch(void* const* d_in, const int* in_sizes, int n_in,
                              void* d_out, int out_size) {
    const float* pred   = (const float*)d_in[0];
    const int*   target = (const int*)d_in[1];
    const float* lv     = (const float*)d_in[2];
    float* out = (float*)d_out;

    dt_kernel<<<BATCH, 512>>>(target);
    loss_partial<<<NLB, LBLK>>>(pred, target);
    loss_final<<<1, 32>>>(lv, out, out_size);
}

// round 3
// speedup vs baseline: 1.3081x; 1.3081x over previous
#include <cuda_runtime.h>
#include <cuda_bf16.h>
#include <math.h>

#define H 512
#define W 512
#define BATCH 16
#define NPIX (H*W)
#define CA 0.955f
#define CB 1.3693f
#define CINF 1e6f
#define BIG 1e30f

#define DT_T 128           // threads in dt kernel
#define CPT 4              // cols per thread
#define NSG 16             // subgroups of 8 lanes

#define LBLK 256
#define BPI 16             // loss blocks per image
#define NLB (BATCH*BPI)

// ---------------- device scratch ----------------
__device__ float g_dist[BATCH*NPIX];
__device__ float g_mx[BATCH];
__device__ int   g_flags[BATCH];
__device__ float g_part[NLB*5];

// 6-bit horizontal window (cols 4t-1 .. 4t+4) from guard-padded row bitmap
__device__ __forceinline__ unsigned win6(const unsigned* mb, int r, int tid) {
    const unsigned* row = mb + r * 18;
    int p = tid * 4 + 31;           // bit position in padded row (guard word 0)
    unsigned lo = row[p >> 5];
    unsigned hi = row[(p >> 5) + 1];
    return __funnelshift_r(lo, hi, p & 31) & 63u;
}

__global__ __launch_bounds__(DT_T) void dt_kernel(const int* __restrict__ target) {
    const int img = blockIdx.x;
    const int* tg = target + img * NPIX;
    float* dd = g_dist + img * NPIX;

    const int tid  = threadIdx.x;
    const int lane = tid & 31;
    const int sg   = tid >> 3;      // subgroup 0..15
    const int sl   = tid & 7;       // lane within subgroup
    const int col0 = tid * CPT;

    __shared__ unsigned mbits[H * 18];       // 36 KB guard-padded bitmap
    __shared__ float prevd[W + 2];
    __shared__ __align__(16) float sg_agg[NSG];
    __shared__ float wred[DT_T / 32];
    __shared__ int sflag[2];

    // ---- init guards / flags ----
    if (tid < 2) sflag[tid] = 0;
    for (int r = tid; r < H; r += DT_T) {
        mbits[r * 18 + 0]  = 0u;
        mbits[r * 18 + 17] = 0u;
    }
    __syncthreads();

    // ---- build bitmap (octet leader stores one 32-col word) ----
    bool any1 = false, any0 = false;
    for (int r = 0; r < H; r++) {
        int4 tv = *(const int4*)(tg + r * W + col0);
        unsigned nib = (unsigned)(tv.x != 0) | ((unsigned)(tv.y != 0) << 1)
                     | ((unsigned)(tv.z != 0) << 2) | ((unsigned)(tv.w != 0) << 3);
        any1 |= (nib != 0u);
        any0 |= (nib != 15u);
        unsigned word = nib << (4 * sl);
        word |= __shfl_xor_sync(0xffffffffu, word, 1);
        word |= __shfl_xor_sync(0xffffffffu, word, 2);
        word |= __shfl_xor_sync(0xffffffffu, word, 4);
        if (sl == 0) mbits[r * 18 + 1 + sg] = word;
    }
    if (__any_sync(0xffffffffu, any1) && lane == 0) atomicOr(&sflag[0], 1);
    if (__any_sync(0xffffffffu, any0) && lane == 0) atomicOr(&sflag[1], 1);
    __syncthreads();
    const int hasb = sflag[0] & sflag[1];

    // edge-fix for AND windows (out-of-bounds treated as foreground for erosion)
    unsigned efix = 0u;
    if (tid == 0) efix |= 1u;
    if (tid == DT_T - 1) efix |= 32u;

    const float aj0 = CA * (float)col0;

    // ---- forward pass ----
    prevd[col0 + 1] = CINF; prevd[col0 + 2] = CINF;
    prevd[col0 + 3] = CINF; prevd[col0 + 4] = CINF;
    if (tid == 0) { prevd[0] = CINF; prevd[W + 1] = CINF; }
    __syncthreads();

    unsigned wAo = 0u, wAa = 63u;
    unsigned wB = win6(mbits, 0, tid), wBa = wB | efix;

    for (int i = 0; i < H; i++) {
        unsigned wC, wCa;
        if (i < H - 1) { wC = win6(mbits, i + 1, tid); wCa = wC | efix; }
        else           { wC = 0u; wCa = 63u; }
        unsigned orW  = wAo | wB | wC;
        unsigned andW = wAa & wBa & wCa;

        float P0 = prevd[col0 + 0], P1 = prevd[col0 + 1], P2 = prevd[col0 + 2];
        float P3 = prevd[col0 + 3], P4 = prevd[col0 + 4], P5 = prevd[col0 + 5];

        float pm[4];
        {
            float Pl[6] = {P0, P1, P2, P3, P4, P5};
            #pragma unroll
            for (int c = 0; c < 4; c++) {
                int seed;
                if (hasb) seed = (((orW >> c) & 7u) != 0u) && (((andW >> c) & 7u) != 7u);
                else      seed = (((wB >> (c + 1)) & 1u) == 0u);
                float drow = seed ? 0.0f : CINF;
                float m = fminf(fminf(drow, Pl[c + 1] + CA),
                                fminf(Pl[c] + CB, Pl[c + 2] + CB));
                float v = m - (aj0 + CA * (float)c);
                pm[c] = (c == 0) ? v : fminf(pm[c - 1], v);
            }
        }
        // 8-lane subgroup inclusive scan of thread aggregates
        float s = pm[3], o;
        o = __shfl_up_sync(0xffffffffu, s, 1); if (sl >= 1) s = fminf(s, o);
        o = __shfl_up_sync(0xffffffffu, s, 2); if (sl >= 2) s = fminf(s, o);
        o = __shfl_up_sync(0xffffffffu, s, 4); if (sl >= 4) s = fminf(s, o);
        float excl = __shfl_up_sync(0xffffffffu, s, 1);
        if (sl == 0) excl = BIG;
        if (sl == 7) sg_agg[sg] = s;
        __syncthreads();

        // masked tree-min over subgroup aggregates with index < sg
        float u[16];
        {
            const float4* sq = (const float4*)sg_agg;
            float4 q0 = sq[0], q1 = sq[1], q2 = sq[2], q3 = sq[3];
            float raw[16] = {q0.x,q0.y,q0.z,q0.w, q1.x,q1.y,q1.z,q1.w,
                             q2.x,q2.y,q2.z,q2.w, q3.x,q3.y,q3.z,q3.w};
            #pragma unroll
            for (int k = 0; k < 16; k++) u[k] = (k < sg) ? raw[k] : BIG;
            #pragma unroll
            for (int st = 8; st > 0; st >>= 1)
                #pragma unroll
                for (int k = 0; k < 8; k++)
                    if (k < st) u[k] = fminf(u[k], u[k + st]);
        }
        float base = fminf(u[0], excl);

        float4 outv;
        outv.x = aj0            + fminf(base, pm[0]);
        outv.y = aj0 + CA*1.0f  + fminf(base, pm[1]);
        outv.z = aj0 + CA*2.0f  + fminf(base, pm[2]);
        outv.w = aj0 + CA*3.0f  + fminf(base, pm[3]);
        *(float4*)(dd + i * W + col0) = outv;
        prevd[col0 + 1] = outv.x; prevd[col0 + 2] = outv.y;
        prevd[col0 + 3] = outv.z; prevd[col0 + 4] = outv.w;

        wAo = wB; wAa = wBa; wB = wC; wBa = wCa;
        __syncthreads();
    }

    // ---- backward pass ----
    prevd[col0 + 1] = CINF; prevd[col0 + 2] = CINF;
    prevd[col0 + 3] = CINF; prevd[col0 + 4] = CINF;
    if (tid == 0) { prevd[0] = CINF; prevd[W + 1] = CINF; }
    __syncthreads();

    const float ar0 = CA * (float)(W - 1 - col0);   // for col0 (decreases with c)
    float lmax = 0.0f;
    float4 nxt = *(const float4*)(dd + (H - 1) * W + col0);

    for (int i = H - 1; i >= 0; i--) {
        float4 drow4 = nxt;
        if (i > 0) nxt = *(const float4*)(dd + (i - 1) * W + col0);

        float P0 = prevd[col0 + 0], P1 = prevd[col0 + 1], P2 = prevd[col0 + 2];
        float P3 = prevd[col0 + 3], P4 = prevd[col0 + 4], P5 = prevd[col0 + 5];

        float pm[4];
        {
            float Pl[6] = {P0, P1, P2, P3, P4, P5};
            float dr[4] = {drow4.x, drow4.y, drow4.z, drow4.w};
            #pragma unroll
            for (int c = 3; c >= 0; c--) {
                float m = fminf(fminf(dr[c], Pl[c + 1] + CA),
                                fminf(Pl[c + 2] + CB, Pl[c] + CB));
                float v = m - (ar0 - CA * (float)c);
                pm[c] = (c == 3) ? v : fminf(pm[c + 1], v);
            }
        }
        // 8-lane subgroup suffix scan
        float s = pm[0], o;
        o = __shfl_down_sync(0xffffffffu, s, 1); if (sl <= 6) s = fminf(s, o);
        o = __shfl_down_sync(0xffffffffu, s, 2); if (sl <= 5) s = fminf(s, o);
        o = __shfl_down_sync(0xffffffffu, s, 4); if (sl <= 3) s = fminf(s, o);
        float excl = __shfl_down_sync(0xffffffffu, s, 1);
        if (sl == 7) excl = BIG;
        if (sl == 0) sg_agg[sg] = s;
        __syncthreads();

        float u[16];
        {
            const float4* sq = (const float4*)sg_agg;
            float4 q0 = sq[0], q1 = sq[1], q2 = sq[2], q3 = sq[3];
            float raw[16] = {q0.x,q0.y,q0.z,q0.w, q1.x,q1.y,q1.z,q1.w,
                             q2.x,q2.y,q2.z,q2.w, q3.x,q3.y,q3.z,q3.w};
            #pragma unroll
            for (int k = 0; k < 16; k++) u[k] = (k > sg) ? raw[k] : BIG;
            #pragma unroll
            for (int st = 8; st > 0; st >>= 1)
                #pragma unroll
                for (int k = 0; k < 8; k++)
                    if (k < st) u[k] = fminf(u[k], u[k + st]);
        }
        float base = fminf(u[0], excl);

        float4 outv;
        outv.x = ar0            + fminf(base, pm[0]);
        outv.y = (ar0 - CA*1.0f) + fminf(base, pm[1]);
        outv.z = (ar0 - CA*2.0f) + fminf(base, pm[2]);
        outv.w = (ar0 - CA*3.0f) + fminf(base, pm[3]);
        *(float4*)(dd + i * W + col0) = outv;
        lmax = fmaxf(fmaxf(fmaxf(outv.x, outv.y), fmaxf(outv.z, outv.w)), lmax);
        prevd[col0 + 1] = outv.x; prevd[col0 + 2] = outv.y;
        prevd[col0 + 3] = outv.z; prevd[col0 + 4] = outv.w;
        __syncthreads();
    }

    // ---- per-image max + flags ----
    #pragma unroll
    for (int d = 16; d > 0; d >>= 1)
        lmax = fmaxf(lmax, __shfl_xor_sync(0xffffffffu, lmax, d));
    if (lane == 0) wred[tid >> 5] = lmax;
    __syncthreads();
    if (tid == 0) {
        float mm = 0.0f;
        for (int w = 0; w < DT_T / 32; w++) mm = fmaxf(mm, wred[w]);
        g_mx[img] = mm;
        g_flags[img] = sflag[0] | (sflag[1] << 1);
    }
}

// ---------------- loss partial sums ----------------
__global__ __launch_bounds__(LBLK) void loss_partial(const float* __restrict__ pred,
                                                     const int* __restrict__ target) {
    const int img = blockIdx.x / BPI;
    const int sub = blockIdx.x % BPI;
    const int base = img * NPIX;
    const float mx = g_mx[img];
    const int hfg = g_flags[img] & 1;
    const float inv = 1.0f / fmaxf(mx, 1e-12f);
    const int usediv = (mx > 0.0f) ? 1 : 0;

    float sF = 0.f, sB = 0.f, sP = 0.f, sT = 0.f, sPT = 0.f;
    for (int idx = sub * LBLK + threadIdx.x; idx < NPIX; idx += BPI * LBLK) {
        float x = pred[base + idx];
        int tv = target[base + idx];
        float d = g_dist[base + idx];
        float p = 1.0f / (1.0f + expf(-x));
        float ax = fabsf(x);
        float bce = log1pf(expf(-ax)) + (tv ? fmaxf(-x, 0.0f) : fmaxf(x, 0.0f));
        float pt = tv ? p : (1.0f - p);
        float omp = 1.0f - pt;
        float alpha = tv ? 0.25f : 0.75f;
        sF += alpha * omp * omp * bce;
        float dn = hfg ? (usediv ? d * inv : d) : 1.0f;
        sB += omp * (1.0f + dn);
        sP += p;
        if (tv) { sT += 1.0f; sPT += p; }
    }

    float vals[5] = {sF, sB, sP, sT, sPT};
    #pragma unroll
    for (int k = 0; k < 5; k++) {
        float v = vals[k];
        #pragma unroll
        for (int d = 16; d > 0; d >>= 1) v += __shfl_xor_sync(0xffffffffu, v, d);
        vals[k] = v;
    }
    __shared__ float s5[LBLK / 32][5];
    int lane = threadIdx.x & 31, wid = threadIdx.x >> 5;
    if (lane == 0) {
        #pragma unroll
        for (int k = 0; k < 5; k++) s5[wid][k] = vals[k];
    }
    __syncthreads();
    if (threadIdx.x == 0) {
        #pragma unroll
        for (int k = 0; k < 5; k++) {
            float a = 0.f;
            for (int w = 0; w < LBLK / 32; w++) a += s5[w][k];
            g_part[blockIdx.x * 5 + k] = a;
        }
    }
}

// ---------------- final combine ----------------
__global__ void loss_final(const float* __restrict__ lv, float* __restrict__ out,
                           int out_size) {
    __shared__ double sd[BATCH][4];
    int t = threadIdx.x;
    if (t < BATCH) {
        double F = 0, Bd = 0, P = 0, T = 0, PT = 0;
        for (int b = 0; b < BPI; b++) {
            const float* pp = g_part + (t * BPI + b) * 5;
            F += pp[0]; Bd += pp[1]; P += pp[2]; T += pp[3]; PT += pp[4];
        }
        double total = P + T;
        double uni = total - PT;
        sd[t][0] = F;
        sd[t][1] = Bd;
        sd[t][2] = (2.0 * PT + 1e-6) / (total + 1e-6);
        sd[t][3] = (PT + 1e-6) / (uni + 1e-6);
    }
    __syncthreads();
    if (t == 0) {
        double F = 0, Bd = 0, D = 0, I = 0;
        for (int b = 0; b < BATCH; b++) {
            F += sd[b][0]; Bd += sd[b][1]; D += sd[b][2]; I += sd[b][3];
        }
        double N = (double)BATCH * (double)NPIX;
        double focal = F / N;
        double bnd   = Bd / N;
        double dice  = 1.0 - D / (double)BATCH;
        double iou   = 1.0 - I / (double)BATCH;
        double l0 = (double)lv[0], l1 = (double)lv[1], l2 = (double)lv[2], l3 = (double)lv[3];
        double tot = exp(-l0) * focal + l0
                   + exp(-l1) * dice  + l1
                   + exp(-l2) * bnd   + l2
                   + exp(-l3) * iou   + l3;
        if (out_size > 0) out[0] = (float)tot;
        if (out_size > 1) out[1] = (float)focal;
        if (out_size > 2) out[2] = (float)dice;
        if (out_size > 3) out[3] = (float)bnd;
        if (out_size > 4) out[4] = (float)iou;
    }
}

extern "C" void kernel_launch(void* const* d_in, const int* in_sizes, int n_in,
                              void* d_out, int out_size) {
    const float* pred   = (const float*)d_in[0];
    const int*   target = (const int*)d_in[1];
    const float* lv     = (const float*)d_in[2];
    float* out = (float*)d_out;

    dt_kernel<<<BATCH, DT_T>>>(target);
    loss_partial<<<NLB, LBLK>>>(pred, target);
    loss_final<<<1, 32>>>(lv, out, out_size);
}